// round 10
// baseline (speedup 1.0000x reference)
#include <cuda_runtime.h>
#include <cuda_fp16.h>
#include <mma.h>
#include <cstdint>
#include <cstddef>

using namespace nvcuda;

// ---------------------------------------------------------------------------
// MegNetBlock — persistent wmma fp16 (A hi/lo 2-pass, exact-fp16 weights)
// 128-row tiles, weights resident in smem.  N=100000, E=800000, D=64, H=128
// ---------------------------------------------------------------------------

#define NMAX 100000
typedef unsigned int u32;

// ---------------- scratch (device globals) ----------------
__device__ float  g_v_pre[NMAX * 64];
__device__ float4 g_As[NMAX * 32];
__device__ float4 g_Ad[NMAX * 32];
__device__ float  g_ve[NMAX * 64];
__device__ float  g_cnt[NMAX];
__device__ float  g_u_pre[64];
__device__ __align__(16) float g_ce[128];
__device__ __align__(16) float g_cn[128];
__device__ float  g_ue[64];
__device__ float  g_uv[64];

// fp16 weights, [k][n] row-major per segment (offsets in elems)
//  0 Wp 0 (64x64) | 1 W0e 4096 (64x128) | 2 W1e 12288 (128x128)
//  3 W2e 28672 (128x64) | 4 W0n 36864 | 5 W1n 53248 | 6 W2n 69632
__device__ __align__(16) __half g_W[77824];

// ---------------- smem layouts (byte offsets) ----------------
static constexpr int SA = 136;   // A row stride in fp16 elems

// edge kernel (512 threads, 16 warps, 128 rows/iter)
static constexpr int E_WP  = 0;        // 64x72   = 9216
static constexpr int E_W0  = 9216;     // 64x136  = 17408
static constexpr int E_W1  = 26624;    // 128x136 = 34816
static constexpr int E_W2  = 61440;    // 128x72  = 18432
static constexpr int E_A_H = 79872;    // 128x136 = 34816
static constexpr int E_A_L = 114688;   // 34816
static constexpr int E_STG = 149504;   // 16 x 16x20 f32 = 20480
static constexpr int E_MISC = 169984;  // src 512|dst 512|pb 256|b1 512|b2 256|ce 512|spart 2048
static constexpr int E_TOTAL = 174592;

// node kernel (512 threads, 128 rows/iter)
static constexpr int N_W0  = 0;        // 34816
static constexpr int N_W1  = 34816;    // 34816
static constexpr int N_W2  = 69632;    // 18432
static constexpr int N_A_H = 88064;    // 34816
static constexpr int N_A_L = 122880;   // 34816
static constexpr int N_STG = 157696;   // 20480
static constexpr int N_MISC = 178176;  // cn 512|b1 512|b2 256|spart 2048
static constexpr int N_TOTAL = 181504;

static constexpr int NUM_CTAS = 148;

// ---------------- helpers ----------------
__device__ __forceinline__ float sp(float x) {
    return fmaxf(x, 0.0f) + __logf(1.0f + __expf(-fabsf(x)));
}
// split two fp32 into packed fp16 hi-pair / lo-pair
__device__ __forceinline__ void split2(float v0, float v1, u32& hi, u32& lo) {
    __half h0 = __float2half_rn(v0), h1 = __float2half_rn(v1);
    __half l0 = __float2half_rn(v0 - __half2float(h0));
    __half l1 = __float2half_rn(v1 - __half2float(h1));
    hi = ((u32)__half_as_ushort(h1) << 16) | __half_as_ushort(h0);
    lo = ((u32)__half_as_ushort(l1) << 16) | __half_as_ushort(l0);
}

typedef wmma::fragment<wmma::matrix_a, 16, 16, 16, __half, wmma::row_major> FragA;
typedef wmma::fragment<wmma::matrix_b, 16, 16, 16, __half, wmma::row_major> FragB;
typedef wmma::fragment<wmma::accumulator, 16, 16, 16, float> FragC;

// C[row0:16, colbase..] = (A_hi + A_lo)[row0:, :K] @ W[:K, cols]  (2-pass)
__device__ __forceinline__ void mma_half(const char* smem, int offAh, int offAl,
                                         int offW, int row0, int K, int SW,
                                         int colbase, int nt, FragC* acc) {
    const __half* Ah = (const __half*)(smem + offAh) + row0 * SA;
    const __half* Al = (const __half*)(smem + offAl) + row0 * SA;
    const __half* W = (const __half*)(smem + offW) + colbase;
    for (int n = 0; n < nt; n++) wmma::fill_fragment(acc[n], 0.0f);
    for (int k = 0; k < K; k += 16) {
        FragA ah, al;
        wmma::load_matrix_sync(ah, Ah + k, SA);
        wmma::load_matrix_sync(al, Al + k, SA);
        for (int n = 0; n < nt; n++) {
            FragB bh;
            wmma::load_matrix_sync(bh, W + k * SW + n * 16, SW);
            wmma::mma_sync(acc[n], ah, bh, acc[n]);
            wmma::mma_sync(acc[n], al, bh, acc[n]);
        }
    }
}

__device__ __forceinline__ void load_W_seg(char* smem, int goff, int K, int N, int SW,
                                           int off, int tid, int nthr) {
    const u32* gw = (const u32*)(g_W + goff);
    int total2 = K * N / 2;
    for (int i2 = tid; i2 < total2; i2 += nthr) {
        int k = (2 * i2) / N, n = (2 * i2) % N;
        *(u32*)(smem + off + (k * SW + n) * 2) = gw[i2];
    }
}

__device__ __forceinline__ void store_A8(char* smem, int offAh, int offAl, int row,
                                         int col, const float* v) {
#pragma unroll
    for (int j = 0; j < 8; j += 2) {
        u32 hi, lo;
        split2(v[j], v[j + 1], hi, lo);
        int d = (row * SA + col + j) * 2;
        *(u32*)(smem + offAh + d) = hi;
        *(u32*)(smem + offAl + d) = lo;
    }
}

// ---------------------------------------------------------------------------
__global__ void zero_kernel(int nNodes) {
    int total = nNodes * 64 + nNodes + 128;
    for (int i = blockIdx.x * blockDim.x + threadIdx.x; i < total;
         i += gridDim.x * blockDim.x) {
        if (i < nNodes * 64) g_ve[i] = 0.0f;
        else if (i < nNodes * 64 + nNodes) g_cnt[i - nNodes * 64] = 0.0f;
        else {
            int j = i - nNodes * 64 - nNodes;
            if (j < 64) g_ue[j] = 0.0f; else g_uv[j - 64] = 0.0f;
        }
    }
}

__global__ void pre_attr_kernel(const float* __restrict__ ga,
                                const float* __restrict__ w,
                                const float* __restrict__ b) {
    __shared__ float sg[64];
    int t = threadIdx.x;
    sg[t] = ga[t];
    __syncthreads();
    float acc = b[t];
    for (int k = 0; k < 64; k++) acc = fmaf(sg[k], w[k * 64 + t], acc);
    g_u_pre[t] = sp(acc);
}

__global__ void const_kernel(const float* __restrict__ ew0,
                             const float* __restrict__ eb0,
                             const float* __restrict__ nw0,
                             const float* __restrict__ nb0) {
    __shared__ float su[64];
    int t = threadIdx.x;  // 128
    if (t < 64) su[t] = g_u_pre[t];
    __syncthreads();
    float a = eb0[t], c = nb0[t];
    for (int k = 0; k < 64; k++) {
        a = fmaf(su[k], ew0[(192 + k) * 128 + t], a);
        c = fmaf(su[k], nw0[(128 + k) * 128 + t], c);
    }
    g_ce[t] = a;
    g_cn[t] = c;
}

__global__ void prep_w_kernel(const float* pw, const float* ew0,
                              const float* ew1, const float* ew2,
                              const float* nw0, const float* nw1,
                              const float* nw2) {
    const float* srcs[7] = {pw, ew0 + 128 * 128, ew1, ew2, nw0, nw1, nw2};
    const int KN[7] = {4096, 8192, 16384, 8192, 16384, 16384, 8192};
    const int off[7] = {0, 4096, 12288, 28672, 36864, 53248, 69632};
#pragma unroll 1
    for (int s = 0; s < 7; s++) {
        const float* sc = srcs[s];
        for (int i = blockIdx.x * blockDim.x + threadIdx.x; i < KN[s];
             i += gridDim.x * blockDim.x)
            g_W[off[s] + i] = __float2half_rn(sc[i]);
    }
}

// ---------------------------------------------------------------------------
__global__ __launch_bounds__(128) void pre_nodeA_kernel(
    const float* __restrict__ nf, const float* __restrict__ pw,
    const float* __restrict__ pb, const float* __restrict__ ew0) {
    __shared__ float snf[2048];
    __shared__ float sv[2048];
    int tid = threadIdx.x;
    size_t base = (size_t)blockIdx.x * 32;

    for (int i = tid; i < 512; i += 128)
        ((float4*)snf)[i] = ((const float4*)(nf + base * 64))[i];
    __syncthreads();

    {
        int col = tid & 63, hf = tid >> 6;
        float bb = pb[col];
        float acc[16];
#pragma unroll
        for (int i = 0; i < 16; i++) acc[i] = bb;
        const float* xr = snf + hf * 16 * 64;
        for (int k = 0; k < 64; k += 4) {
            float wa = __ldg(pw + k * 64 + col), wb = __ldg(pw + (k + 1) * 64 + col);
            float wc = __ldg(pw + (k + 2) * 64 + col), wd = __ldg(pw + (k + 3) * 64 + col);
#pragma unroll
            for (int i = 0; i < 16; i++) {
                float4 xv = *(const float4*)(xr + i * 64 + k);
                acc[i] = fmaf(xv.x, wa, acc[i]);
                acc[i] = fmaf(xv.y, wb, acc[i]);
                acc[i] = fmaf(xv.z, wc, acc[i]);
                acc[i] = fmaf(xv.w, wd, acc[i]);
            }
        }
#pragma unroll
        for (int i = 0; i < 16; i++) {
            float v = sp(acc[i]);
            sv[(hf * 16 + i) * 64 + col] = v;
            g_v_pre[(base + hf * 16 + i) * 64 + col] = v;
        }
    }
    __syncthreads();

    float* Asf = (float*)g_As;
    float* Adf = (float*)g_Ad;
    int j = tid;
#pragma unroll 1
    for (int m = 0; m < 2; m++) {
        const float* w = ew0 + (size_t)m * 64 * 128;
        float acc[32];
#pragma unroll
        for (int e = 0; e < 32; e++) acc[e] = 0.0f;
        for (int k = 0; k < 64; k += 4) {
            float wa = __ldg(w + k * 128 + j), wb = __ldg(w + (k + 1) * 128 + j);
            float wc = __ldg(w + (k + 2) * 128 + j), wd = __ldg(w + (k + 3) * 128 + j);
#pragma unroll
            for (int e = 0; e < 32; e++) {
                float4 xv = *(const float4*)(sv + e * 64 + k);
                acc[e] = fmaf(xv.x, wa, acc[e]);
                acc[e] = fmaf(xv.y, wb, acc[e]);
                acc[e] = fmaf(xv.z, wc, acc[e]);
                acc[e] = fmaf(xv.w, wd, acc[e]);
            }
        }
        float* dstp = m ? Adf : Asf;
#pragma unroll
        for (int e = 0; e < 32; e++) dstp[(base + e) * 128 + j] = acc[e];
    }
}

// ---------------------------------------------------------------------------
// persistent edge kernel: 128 edges / iteration, 512 threads / 16 warps
// warp = (slab 0..7, h 0..1): rows slab*16..+16, cols h*(N/2)..
// ---------------------------------------------------------------------------
__global__ __launch_bounds__(512) void edge_kernel(
    const float* __restrict__ ef, const int* __restrict__ srcI,
    const int* __restrict__ dstI, const float* __restrict__ pb,
    const float* __restrict__ b1, const float* __restrict__ b2,
    float* __restrict__ e_out, int nTiles) {
    extern __shared__ char smem[];
    int tid = threadIdx.x, wid = tid >> 5, lane = tid & 31;

    int*   s_src = (int*)(smem + E_MISC);
    int*   s_dst = (int*)(smem + E_MISC + 512);
    float* s_pb  = (float*)(smem + E_MISC + 1024);
    float* s_b1  = (float*)(smem + E_MISC + 1280);
    float* s_b2  = (float*)(smem + E_MISC + 1792);
    float* s_ce  = (float*)(smem + E_MISC + 2048);
    float* spart = (float*)(smem + E_MISC + 2560);
    float* stg   = (float*)(smem + E_STG) + wid * 320;
    float* fstage = (float*)(smem + E_A_H);  // f32 [128][68]

    load_W_seg(smem, 0,     64, 64,  72, E_WP, tid, 512);
    load_W_seg(smem, 4096,  64, 128, 136, E_W0, tid, 512);
    load_W_seg(smem, 12288, 128, 128, 136, E_W1, tid, 512);
    load_W_seg(smem, 28672, 128, 64,  72, E_W2, tid, 512);
    if (tid < 128) {
        s_ce[tid] = g_ce[tid];
        s_b1[tid] = __ldg(b1 + tid);
    } else if (tid < 192) {
        s_pb[tid - 128] = __ldg(pb + tid - 128);
    } else if (tid < 256) {
        s_b2[tid - 192] = __ldg(b2 + tid - 192);
    }

    int slab = wid & 7, h = wid >> 3, row0 = slab * 16;
    int r = lane >> 1, c0 = (lane & 1) * 8, row = row0 + r;
    float ue_acc = 0.0f;
    FragC acc[4];

    for (int t = blockIdx.x; t < nTiles; t += gridDim.x) {
        size_t base = (size_t)t * 128;
        __syncthreads();

        if (tid < 128) {
            s_src[tid] = srcI[base + tid];
            s_dst[tid] = dstI[base + tid];
        }
        // stage ef -> A hi/lo: 2048 float4s
        for (int i = tid; i < 2048; i += 512) {
            int rr = i >> 4, q = i & 15;
            float4 v = __ldg((const float4*)(ef + (base + rr) * 64) + q);
            int c = q * 4;
            u32 hi, lo;
            split2(v.x, v.y, hi, lo);
            *(u32*)(smem + E_A_H + (rr * SA + c) * 2) = hi;
            *(u32*)(smem + E_A_L + (rr * SA + c) * 2) = lo;
            split2(v.z, v.w, hi, lo);
            *(u32*)(smem + E_A_H + (rr * SA + c + 2) * 2) = hi;
            *(u32*)(smem + E_A_L + (rr * SA + c + 2) * 2) = lo;
        }
        __syncthreads();

        // ---- phase 0: pre-edge K=64 N=64 ----
        mma_half(smem, E_A_H, E_A_L, E_WP, row0, 64, 72, h * 32, 2, acc);
        __syncthreads();
#pragma unroll
        for (int n = 0; n < 2; n++) {
            wmma::store_matrix_sync(stg, acc[n], 20, wmma::mem_row_major);
            __syncwarp();
            int col = h * 32 + n * 16 + c0;
            float v[8];
#pragma unroll
            for (int j = 0; j < 8; j++) v[j] = sp(stg[r * 20 + c0 + j] + s_pb[col + j]);
            store_A8(smem, E_A_H, E_A_L, row, col, v);
            __syncwarp();
        }
        __syncthreads();

        // ---- phase 1: L0 K=64 N=128 (+ As[src]+Ad[dst]+ce) ----
        mma_half(smem, E_A_H, E_A_L, E_W0, row0, 64, 136, h * 64, 4, acc);
        __syncthreads();
        {
            const float4* as4 = (const float4*)g_As + (size_t)s_src[row] * 32;
            const float4* ad4 = (const float4*)g_Ad + (size_t)s_dst[row] * 32;
#pragma unroll
            for (int n = 0; n < 4; n++) {
                wmma::store_matrix_sync(stg, acc[n], 20, wmma::mem_row_major);
                __syncwarp();
                int col = h * 64 + n * 16 + c0;
                float4 a0 = __ldg(as4 + (col >> 2)), a1 = __ldg(as4 + (col >> 2) + 1);
                float4 d0 = __ldg(ad4 + (col >> 2)), d1 = __ldg(ad4 + (col >> 2) + 1);
                float ga[8] = {a0.x + d0.x, a0.y + d0.y, a0.z + d0.z, a0.w + d0.w,
                               a1.x + d1.x, a1.y + d1.y, a1.z + d1.z, a1.w + d1.w};
                float v[8];
#pragma unroll
                for (int j = 0; j < 8; j++)
                    v[j] = sp(stg[r * 20 + c0 + j] + ga[j] + s_ce[col + j]);
                store_A8(smem, E_A_H, E_A_L, row, col, v);
                __syncwarp();
            }
        }
        __syncthreads();

        // ---- phase 2: L1 K=128 N=128 ----
        mma_half(smem, E_A_H, E_A_L, E_W1, row0, 128, 136, h * 64, 4, acc);
        __syncthreads();
#pragma unroll
        for (int n = 0; n < 4; n++) {
            wmma::store_matrix_sync(stg, acc[n], 20, wmma::mem_row_major);
            __syncwarp();
            int col = h * 64 + n * 16 + c0;
            float v[8];
#pragma unroll
            for (int j = 0; j < 8; j++) v[j] = sp(stg[r * 20 + c0 + j] + s_b1[col + j]);
            store_A8(smem, E_A_H, E_A_L, row, col, v);
            __syncwarp();
        }
        __syncthreads();

        // ---- phase 3: L2 K=128 N=64 ----
        mma_half(smem, E_A_H, E_A_L, E_W2, row0, 128, 72, h * 32, 2, acc);
        __syncthreads();
        {
            int dnode = s_dst[row];
#pragma unroll
            for (int n = 0; n < 2; n++) {
                wmma::store_matrix_sync(stg, acc[n], 20, wmma::mem_row_major);
                __syncwarp();
                int col = h * 32 + n * 16 + c0;
                float v[8];
#pragma unroll
                for (int j = 0; j < 8; j++)
                    v[j] = sp(stg[r * 20 + c0 + j] + s_b2[col + j]);
                size_t gidx = (base + row) * 64 + col;
                float4 e0 = __ldg((const float4*)(ef + gidx));
                float4 e1 = __ldg((const float4*)(ef + gidx) + 1);
                float4 o0 = {v[0] + e0.x, v[1] + e0.y, v[2] + e0.z, v[3] + e0.w};
                float4 o1 = {v[4] + e1.x, v[5] + e1.y, v[6] + e1.z, v[7] + e1.w};
                *(float4*)(e_out + gidx) = o0;
                *((float4*)(e_out + gidx) + 1) = o1;
                float* vrow = &g_ve[(size_t)dnode * 64 + col];
#pragma unroll
                for (int j = 0; j < 8; j++) {
                    atomicAdd(vrow + j, v[j]);
                    fstage[row * 68 + col + j] = v[j];
                }
                if (n == 0 && h == 0 && (lane & 1) == 0)
                    atomicAdd(&g_cnt[dnode], 1.0f);
                __syncwarp();
            }
        }
        __syncthreads();

        // ue partial: 512 threads, 16 rows each
        {
            int col = tid & 63, q = tid >> 6;
            float s = 0.0f;
#pragma unroll
            for (int rr = q * 16; rr < q * 16 + 16; rr++) s += fstage[rr * 68 + col];
            spart[tid] = s;
        }
        __syncthreads();
        if (tid < 64) {
            float s = 0.0f;
#pragma unroll
            for (int q = 0; q < 8; q++) s += spart[q * 64 + tid];
            ue_acc += s;
        }
    }
    if (tid < 64) atomicAdd(&g_ue[tid], ue_acc);
}

// ---------------------------------------------------------------------------
// persistent node kernel: 128 nodes / iteration, 512 threads
// ---------------------------------------------------------------------------
__global__ __launch_bounds__(512) void node_kernel(
    const float* __restrict__ nf, const float* __restrict__ b1,
    const float* __restrict__ b2, float* __restrict__ v_out, int nNodes,
    int nTiles) {
    extern __shared__ char smem[];
    int tid = threadIdx.x, wid = tid >> 5, lane = tid & 31;

    float* s_cn  = (float*)(smem + N_MISC);
    float* s_b1  = (float*)(smem + N_MISC + 512);
    float* s_b2  = (float*)(smem + N_MISC + 1024);
    float* spart = (float*)(smem + N_MISC + 1280);
    float* stg   = (float*)(smem + N_STG) + wid * 320;
    float* fstage = (float*)(smem + N_A_H);

    load_W_seg(smem, 36864, 128, 128, 136, N_W0, tid, 512);
    load_W_seg(smem, 53248, 128, 128, 136, N_W1, tid, 512);
    load_W_seg(smem, 69632, 128, 64,  72, N_W2, tid, 512);
    if (tid < 128) {
        s_cn[tid] = g_cn[tid];
        s_b1[tid] = __ldg(b1 + tid);
    } else if (tid < 192) {
        s_b2[tid - 128] = (tid - 128 < 64) ? __ldg(b2 + tid - 128) : 0.0f;
    }

    int slab = wid & 7, h = wid >> 3, row0 = slab * 16;
    int r = lane >> 1, c0 = (lane & 1) * 8, row = row0 + r;
    float uv_acc = 0.0f;
    FragC acc[4];

    for (int t = blockIdx.x; t < nTiles; t += gridDim.x) {
        size_t base = (size_t)t * 128;
        __syncthreads();

        // stage X = [v_pre | ve_mean] (K=128): rows 128, each thread 32 cols
        {
            int rr = tid & 127, hh = tid >> 7;  // hh 0..3
            size_t gn = base + rr;
            if (gn >= (size_t)nNodes) gn = nNodes - 1;
            const float4* g4;
            float scale = 1.0f;
            if (hh < 2) {
                g4 = (const float4*)(g_v_pre + gn * 64) + hh * 8;
            } else {
                g4 = (const float4*)(g_ve + gn * 64) + (hh - 2) * 8;
                scale = 1.0f / fmaxf(g_cnt[gn], 1.0f);
            }
#pragma unroll
            for (int q = 0; q < 8; q++) {
                float4 v = __ldg(g4 + q);
                v.x *= scale; v.y *= scale; v.z *= scale; v.w *= scale;
                int c = hh * 32 + q * 4;
                u32 hi, lo;
                split2(v.x, v.y, hi, lo);
                *(u32*)(smem + N_A_H + (rr * SA + c) * 2) = hi;
                *(u32*)(smem + N_A_L + (rr * SA + c) * 2) = lo;
                split2(v.z, v.w, hi, lo);
                *(u32*)(smem + N_A_H + (rr * SA + c + 2) * 2) = hi;
                *(u32*)(smem + N_A_L + (rr * SA + c + 2) * 2) = lo;
            }
        }
        __syncthreads();

        bool valid = (base + row) < (size_t)nNodes;

        // ---- L0: K=128 N=128 ----
        mma_half(smem, N_A_H, N_A_L, N_W0, row0, 128, 136, h * 64, 4, acc);
        __syncthreads();
#pragma unroll
        for (int n = 0; n < 4; n++) {
            wmma::store_matrix_sync(stg, acc[n], 20, wmma::mem_row_major);
            __syncwarp();
            int col = h * 64 + n * 16 + c0;
            float v[8];
#pragma unroll
            for (int j = 0; j < 8; j++) v[j] = sp(stg[r * 20 + c0 + j] + s_cn[col + j]);
            store_A8(smem, N_A_H, N_A_L, row, col, v);
            __syncwarp();
        }
        __syncthreads();

        // ---- L1: K=128 N=128 ----
        mma_half(smem, N_A_H, N_A_L, N_W1, row0, 128, 136, h * 64, 4, acc);
        __syncthreads();
#pragma unroll
        for (int n = 0; n < 4; n++) {
            wmma::store_matrix_sync(stg, acc[n], 20, wmma::mem_row_major);
            __syncwarp();
            int col = h * 64 + n * 16 + c0;
            float v[8];
#pragma unroll
            for (int j = 0; j < 8; j++) v[j] = sp(stg[r * 20 + c0 + j] + s_b1[col + j]);
            store_A8(smem, N_A_H, N_A_L, row, col, v);
            __syncwarp();
        }
        __syncthreads();

        // ---- L2: K=128 N=64 ----
        mma_half(smem, N_A_H, N_A_L, N_W2, row0, 128, 72, h * 32, 2, acc);
        __syncthreads();
#pragma unroll
        for (int n = 0; n < 2; n++) {
            wmma::store_matrix_sync(stg, acc[n], 20, wmma::mem_row_major);
            __syncwarp();
            int col = h * 32 + n * 16 + c0;
            float v[8];
#pragma unroll
            for (int j = 0; j < 8; j++) v[j] = sp(stg[r * 20 + c0 + j] + s_b2[col + j]);
            if (valid) {
                size_t gidx = (base + row) * 64 + col;
                float4 e0 = __ldg((const float4*)(nf + gidx));
                float4 e1 = __ldg((const float4*)(nf + gidx) + 1);
                float4 o0 = {v[0] + e0.x, v[1] + e0.y, v[2] + e0.z, v[3] + e0.w};
                float4 o1 = {v[4] + e1.x, v[5] + e1.y, v[6] + e1.z, v[7] + e1.w};
                *(float4*)(v_out + gidx) = o0;
                *((float4*)(v_out + gidx) + 1) = o1;
            }
#pragma unroll
            for (int j = 0; j < 8; j++)
                fstage[row * 68 + col + j] = valid ? v[j] : 0.0f;
            __syncwarp();
        }
        __syncthreads();

        {
            int col = tid & 63, q = tid >> 6;
            float s = 0.0f;
#pragma unroll
            for (int rr = q * 16; rr < q * 16 + 16; rr++) s += fstage[rr * 68 + col];
            spart[tid] = s;
        }
        __syncthreads();
        if (tid < 64) {
            float s = 0.0f;
#pragma unroll
            for (int q = 0; q < 8; q++) s += spart[q * 64 + tid];
            uv_acc += s;
        }
    }
    if (tid < 64) atomicAdd(&g_uv[tid], uv_acc);
}

// ---------------------------------------------------------------------------
__global__ void attr_kernel(const float* __restrict__ ga,
                            const float* __restrict__ w0,
                            const float* __restrict__ b0,
                            const float* __restrict__ w1,
                            const float* __restrict__ b1,
                            const float* __restrict__ w2,
                            const float* __restrict__ b2,
                            float* __restrict__ out, float invE, float invN) {
    __shared__ float x[192], h0[128], h1[128];
    int t = threadIdx.x;
    if (t < 64) {
        x[t]       = g_u_pre[t];
        x[64 + t]  = g_ue[t] * invE;
        x[128 + t] = g_uv[t] * invN;
    }
    __syncthreads();
    float acc = b0[t];
    for (int k = 0; k < 192; k++) acc = fmaf(x[k], w0[k * 128 + t], acc);
    h0[t] = sp(acc);
    __syncthreads();
    acc = b1[t];
    for (int k = 0; k < 128; k++) acc = fmaf(h0[k], w1[k * 128 + t], acc);
    h1[t] = sp(acc);
    __syncthreads();
    if (t < 64) {
        float a = b2[t];
        for (int k = 0; k < 128; k++) a = fmaf(h1[k], w2[k * 64 + t], a);
        out[t] = sp(a) + ga[t];
    }
}

// ---------------------------------------------------------------------------
extern "C" void kernel_launch(void* const* d_in, const int* in_sizes, int n_in,
                              void* d_out, int out_size) {
    const float* edge_feat  = (const float*)d_in[0];
    const float* node_feat  = (const float*)d_in[1];
    const float* graph_attr = (const float*)d_in[2];
    const int*   src        = (const int*)d_in[3];
    const int*   dst        = (const int*)d_in[4];
    const float* pre_edge_w = (const float*)d_in[5];
    const float* pre_edge_b = (const float*)d_in[6];
    const float* pre_node_w = (const float*)d_in[7];
    const float* pre_node_b = (const float*)d_in[8];
    const float* pre_attr_w = (const float*)d_in[9];
    const float* pre_attr_b = (const float*)d_in[10];
    const float* edge_w0 = (const float*)d_in[11];
    const float* edge_b0 = (const float*)d_in[12];
    const float* edge_w1 = (const float*)d_in[13];
    const float* edge_b1 = (const float*)d_in[14];
    const float* edge_w2 = (const float*)d_in[15];
    const float* edge_b2 = (const float*)d_in[16];
    const float* node_w0 = (const float*)d_in[17];
    const float* node_b0 = (const float*)d_in[18];
    const float* node_w1 = (const float*)d_in[19];
    const float* node_b1 = (const float*)d_in[20];
    const float* node_w2 = (const float*)d_in[21];
    const float* node_b2 = (const float*)d_in[22];
    const float* attr_w0 = (const float*)d_in[23];
    const float* attr_b0 = (const float*)d_in[24];
    const float* attr_w1 = (const float*)d_in[25];
    const float* attr_b1 = (const float*)d_in[26];
    const float* attr_w2 = (const float*)d_in[27];
    const float* attr_b2 = (const float*)d_in[28];

    float* out = (float*)d_out;
    int E = in_sizes[3];
    int N = in_sizes[1] / 64;
    int eTiles = E / 128;
    int nTiles = (N + 127) / 128;

    cudaFuncSetAttribute(edge_kernel, cudaFuncAttributeMaxDynamicSharedMemorySize,
                         E_TOTAL);
    cudaFuncSetAttribute(node_kernel, cudaFuncAttributeMaxDynamicSharedMemorySize,
                         N_TOTAL);

    zero_kernel<<<256, 256>>>(N);
    pre_attr_kernel<<<1, 64>>>(graph_attr, pre_attr_w, pre_attr_b);
    const_kernel<<<1, 128>>>(edge_w0, edge_b0, node_w0, node_b0);
    prep_w_kernel<<<64, 256>>>(pre_edge_w, edge_w0, edge_w1, edge_w2, node_w0,
                               node_w1, node_w2);
    pre_nodeA_kernel<<<N / 32, 128>>>(node_feat, pre_node_w, pre_node_b, edge_w0);
    edge_kernel<<<NUM_CTAS, 512, E_TOTAL>>>(edge_feat, src, dst, pre_edge_b,
                                            edge_b1, edge_b2, out, eTiles);
    node_kernel<<<NUM_CTAS, 512, N_TOTAL>>>(node_feat, node_b1, node_b2,
                                            out + (size_t)E * 64, N, nTiles);
    attr_kernel<<<1, 128>>>(graph_attr, attr_w0, attr_b0, attr_w1, attr_b1,
                            attr_w2, attr_b2,
                            out + (size_t)E * 64 + (size_t)N * 64,
                            1.0f / (float)E, 1.0f / (float)N);
}

// round 11
// speedup vs baseline: 1.1826x; 1.1826x over previous
#include <cuda_runtime.h>
#include <cuda_fp16.h>
#include <mma.h>
#include <cstdint>
#include <cstddef>

using namespace nvcuda;

// ---------------------------------------------------------------------------
// MegNetBlock — persistent wmma fp16 single-pass, ping-pong activation bufs
// N=100000, E=800000, D=64, H=128
// ---------------------------------------------------------------------------

#define NMAX 100000
typedef unsigned int u32;

// ---------------- scratch (device globals) ----------------
__device__ float  g_v_pre[NMAX * 64];
__device__ float4 g_As[NMAX * 32];
__device__ float4 g_Ad[NMAX * 32];
__device__ float  g_ve[NMAX * 64];
__device__ float  g_cnt[NMAX];
__device__ float  g_u_pre[64];
__device__ __align__(16) float g_ce[128];
__device__ __align__(16) float g_cn[128];
__device__ float  g_ue[64];
__device__ float  g_uv[64];

// fp16 weights, [k][n] row-major per segment (offsets in elems)
//  0 Wp 0 (64x64) | 1 W0e 4096 (64x128) | 2 W1e 12288 (128x128)
//  3 W2e 28672 (128x64) | 4 W0n 36864 | 5 W1n 53248 | 6 W2n 69632
__device__ __align__(16) __half g_W[77824];

// ---------------- smem layouts (byte offsets) ----------------
static constexpr int SA = 136;   // A row stride in fp16 elems

// edge kernel (512 threads, 16 warps, 128 rows/iter)
static constexpr int E_WP  = 0;        // 64x72   = 9216
static constexpr int E_W0  = 9216;     // 64x136  = 17408
static constexpr int E_W1  = 26624;    // 128x136 = 34816
static constexpr int E_W2  = 61440;    // 128x72  = 18432
static constexpr int E_A0  = 79872;    // 128x136 fp16 = 34816
static constexpr int E_A1  = 114688;   // 34816
static constexpr int E_STG = 149504;   // 16 x 16x20 f32 = 20480
static constexpr int E_MISC = 169984;  // src|dst|pb|b1|b2|ce|spart
static constexpr int E_TOTAL = 174592;

// node kernel (512 threads, 128 rows/iter)
static constexpr int N_W0  = 0;        // 34816
static constexpr int N_W1  = 34816;    // 34816
static constexpr int N_W2  = 69632;    // 18432
static constexpr int N_A0  = 88064;    // 34816
static constexpr int N_A1  = 122880;   // 34816
static constexpr int N_STG = 157696;   // 20480
static constexpr int N_MISC = 178176;  // cn|b1|b2|spart
static constexpr int N_TOTAL = 182784;

static constexpr int NUM_CTAS = 148;

// ---------------- helpers ----------------
__device__ __forceinline__ float sp(float x) {
    return fmaxf(x, 0.0f) + __logf(1.0f + __expf(-fabsf(x)));
}
__device__ __forceinline__ u32 pack2h(float a, float b) {
    __half2 h = __floats2half2_rn(a, b);
    return *(u32*)&h;
}

typedef wmma::fragment<wmma::matrix_a, 16, 16, 16, __half, wmma::row_major> FragA;
typedef wmma::fragment<wmma::matrix_b, 16, 16, 16, __half, wmma::row_major> FragB;
typedef wmma::fragment<wmma::accumulator, 16, 16, 16, float> FragC;

// C[row0:16, colbase..] = A[row0:, :K] @ W[:K, cols]  (single pass)
__device__ __forceinline__ void mma_half(const char* smem, int offA, int offW,
                                         int row0, int K, int SW, int colbase,
                                         int nt, FragC* acc) {
    const __half* A = (const __half*)(smem + offA) + row0 * SA;
    const __half* W = (const __half*)(smem + offW) + colbase;
    for (int n = 0; n < nt; n++) wmma::fill_fragment(acc[n], 0.0f);
    for (int k = 0; k < K; k += 16) {
        FragA a;
        wmma::load_matrix_sync(a, A + k, SA);
        for (int n = 0; n < nt; n++) {
            FragB b;
            wmma::load_matrix_sync(b, W + k * SW + n * 16, SW);
            wmma::mma_sync(acc[n], a, b, acc[n]);
        }
    }
}

__device__ __forceinline__ void load_W_seg(char* smem, int goff, int K, int N, int SW,
                                           int off, int tid, int nthr) {
    const u32* gw = (const u32*)(g_W + goff);
    int total2 = K * N / 2;
    for (int i2 = tid; i2 < total2; i2 += nthr) {
        int k = (2 * i2) / N, n = (2 * i2) % N;
        *(u32*)(smem + off + (k * SW + n) * 2) = gw[i2];
    }
}

__device__ __forceinline__ void store_A8(char* smem, int offA, int row, int col,
                                         const float* v) {
#pragma unroll
    for (int j = 0; j < 8; j += 2)
        *(u32*)(smem + offA + (row * SA + col + j) * 2) = pack2h(v[j], v[j + 1]);
}

// ---------------------------------------------------------------------------
__global__ void zero_kernel(int nNodes) {
    int total = nNodes * 64 + nNodes + 128;
    for (int i = blockIdx.x * blockDim.x + threadIdx.x; i < total;
         i += gridDim.x * blockDim.x) {
        if (i < nNodes * 64) g_ve[i] = 0.0f;
        else if (i < nNodes * 64 + nNodes) g_cnt[i - nNodes * 64] = 0.0f;
        else {
            int j = i - nNodes * 64 - nNodes;
            if (j < 64) g_ue[j] = 0.0f; else g_uv[j - 64] = 0.0f;
        }
    }
}

__global__ void pre_attr_kernel(const float* __restrict__ ga,
                                const float* __restrict__ w,
                                const float* __restrict__ b) {
    __shared__ float sg[64];
    int t = threadIdx.x;
    sg[t] = ga[t];
    __syncthreads();
    float acc = b[t];
    for (int k = 0; k < 64; k++) acc = fmaf(sg[k], w[k * 64 + t], acc);
    g_u_pre[t] = sp(acc);
}

__global__ void const_kernel(const float* __restrict__ ew0,
                             const float* __restrict__ eb0,
                             const float* __restrict__ nw0,
                             const float* __restrict__ nb0) {
    __shared__ float su[64];
    int t = threadIdx.x;  // 128
    if (t < 64) su[t] = g_u_pre[t];
    __syncthreads();
    float a = eb0[t], c = nb0[t];
    for (int k = 0; k < 64; k++) {
        a = fmaf(su[k], ew0[(192 + k) * 128 + t], a);
        c = fmaf(su[k], nw0[(128 + k) * 128 + t], c);
    }
    g_ce[t] = a;
    g_cn[t] = c;
}

__global__ void prep_w_kernel(const float* pw, const float* ew0,
                              const float* ew1, const float* ew2,
                              const float* nw0, const float* nw1,
                              const float* nw2) {
    const float* srcs[7] = {pw, ew0 + 128 * 128, ew1, ew2, nw0, nw1, nw2};
    const int KN[7] = {4096, 8192, 16384, 8192, 16384, 16384, 8192};
    const int off[7] = {0, 4096, 12288, 28672, 36864, 53248, 69632};
#pragma unroll 1
    for (int s = 0; s < 7; s++) {
        const float* sc = srcs[s];
        for (int i = blockIdx.x * blockDim.x + threadIdx.x; i < KN[s];
             i += gridDim.x * blockDim.x)
            g_W[off[s] + i] = __float2half_rn(sc[i]);
    }
}

// ---------------------------------------------------------------------------
__global__ __launch_bounds__(128) void pre_nodeA_kernel(
    const float* __restrict__ nf, const float* __restrict__ pw,
    const float* __restrict__ pb, const float* __restrict__ ew0) {
    __shared__ float snf[2048];
    __shared__ float sv[2048];
    int tid = threadIdx.x;
    size_t base = (size_t)blockIdx.x * 32;

    for (int i = tid; i < 512; i += 128)
        ((float4*)snf)[i] = ((const float4*)(nf + base * 64))[i];
    __syncthreads();

    {
        int col = tid & 63, hf = tid >> 6;
        float bb = pb[col];
        float acc[16];
#pragma unroll
        for (int i = 0; i < 16; i++) acc[i] = bb;
        const float* xr = snf + hf * 16 * 64;
        for (int k = 0; k < 64; k += 4) {
            float wa = __ldg(pw + k * 64 + col), wb = __ldg(pw + (k + 1) * 64 + col);
            float wc = __ldg(pw + (k + 2) * 64 + col), wd = __ldg(pw + (k + 3) * 64 + col);
#pragma unroll
            for (int i = 0; i < 16; i++) {
                float4 xv = *(const float4*)(xr + i * 64 + k);
                acc[i] = fmaf(xv.x, wa, acc[i]);
                acc[i] = fmaf(xv.y, wb, acc[i]);
                acc[i] = fmaf(xv.z, wc, acc[i]);
                acc[i] = fmaf(xv.w, wd, acc[i]);
            }
        }
#pragma unroll
        for (int i = 0; i < 16; i++) {
            float v = sp(acc[i]);
            sv[(hf * 16 + i) * 64 + col] = v;
            g_v_pre[(base + hf * 16 + i) * 64 + col] = v;
        }
    }
    __syncthreads();

    float* Asf = (float*)g_As;
    float* Adf = (float*)g_Ad;
    int j = tid;
#pragma unroll 1
    for (int m = 0; m < 2; m++) {
        const float* w = ew0 + (size_t)m * 64 * 128;
        float acc[32];
#pragma unroll
        for (int e = 0; e < 32; e++) acc[e] = 0.0f;
        for (int k = 0; k < 64; k += 4) {
            float wa = __ldg(w + k * 128 + j), wb = __ldg(w + (k + 1) * 128 + j);
            float wc = __ldg(w + (k + 2) * 128 + j), wd = __ldg(w + (k + 3) * 128 + j);
#pragma unroll
            for (int e = 0; e < 32; e++) {
                float4 xv = *(const float4*)(sv + e * 64 + k);
                acc[e] = fmaf(xv.x, wa, acc[e]);
                acc[e] = fmaf(xv.y, wb, acc[e]);
                acc[e] = fmaf(xv.z, wc, acc[e]);
                acc[e] = fmaf(xv.w, wd, acc[e]);
            }
        }
        float* dstp = m ? Adf : Asf;
#pragma unroll
        for (int e = 0; e < 32; e++) dstp[(base + e) * 128 + j] = acc[e];
    }
}

// ---------------------------------------------------------------------------
// persistent edge kernel: 128 edges / iteration, 512 threads / 16 warps
// ping-pong: p0 A0->A1, p1 A1->A0, p2 A0->A1, p3 A1->fstage(A0)
// ---------------------------------------------------------------------------
__global__ __launch_bounds__(512) void edge_kernel(
    const float* __restrict__ ef, const int* __restrict__ srcI,
    const int* __restrict__ dstI, const float* __restrict__ pb,
    const float* __restrict__ b1, const float* __restrict__ b2,
    float* __restrict__ e_out, int nTiles) {
    extern __shared__ char smem[];
    int tid = threadIdx.x, wid = tid >> 5, lane = tid & 31;

    int*   s_src = (int*)(smem + E_MISC);
    int*   s_dst = (int*)(smem + E_MISC + 512);
    float* s_pb  = (float*)(smem + E_MISC + 1024);
    float* s_b1  = (float*)(smem + E_MISC + 1280);
    float* s_b2  = (float*)(smem + E_MISC + 1792);
    float* s_ce  = (float*)(smem + E_MISC + 2048);
    float* spart = (float*)(smem + E_MISC + 2560);
    float* stg   = (float*)(smem + E_STG) + wid * 320;
    float* fstage = (float*)(smem + E_A0);  // f32 [128][68]

    load_W_seg(smem, 0,     64, 64,  72, E_WP, tid, 512);
    load_W_seg(smem, 4096,  64, 128, 136, E_W0, tid, 512);
    load_W_seg(smem, 12288, 128, 128, 136, E_W1, tid, 512);
    load_W_seg(smem, 28672, 128, 64,  72, E_W2, tid, 512);
    if (tid < 128) {
        s_ce[tid] = g_ce[tid];
        s_b1[tid] = __ldg(b1 + tid);
    } else if (tid < 192) {
        s_pb[tid - 128] = __ldg(pb + tid - 128);
    } else if (tid < 256) {
        s_b2[tid - 192] = __ldg(b2 + tid - 192);
    }

    int slab = wid & 7, h = wid >> 3, row0 = slab * 16;
    int r = lane >> 1, c0 = (lane & 1) * 8, row = row0 + r;
    float ue_acc = 0.0f;
    FragC acc[4];

    for (int t = blockIdx.x; t < nTiles; t += gridDim.x) {
        size_t base = (size_t)t * 128;
        __syncthreads();  // buf A0 free (prev ue-reduce done); W visible

        if (tid < 128) {
            s_src[tid] = srcI[base + tid];
            s_dst[tid] = dstI[base + tid];
        }
        // stage ef -> A0: 2048 float4s
        for (int i = tid; i < 2048; i += 512) {
            int rr = i >> 4, q = i & 15;
            float4 v = __ldg((const float4*)(ef + (base + rr) * 64) + q);
            int c = q * 4;
            *(u32*)(smem + E_A0 + (rr * SA + c) * 2) = pack2h(v.x, v.y);
            *(u32*)(smem + E_A0 + (rr * SA + c + 2) * 2) = pack2h(v.z, v.w);
        }
        __syncthreads();

        // ---- phase 0: pre-edge K=64 N=64, A0 -> A1 ----
        mma_half(smem, E_A0, E_WP, row0, 64, 72, h * 32, 2, acc);
#pragma unroll
        for (int n = 0; n < 2; n++) {
            wmma::store_matrix_sync(stg, acc[n], 20, wmma::mem_row_major);
            __syncwarp();
            int col = h * 32 + n * 16 + c0;
            float v[8];
#pragma unroll
            for (int j = 0; j < 8; j++) v[j] = sp(stg[r * 20 + c0 + j] + s_pb[col + j]);
            store_A8(smem, E_A1, row, col, v);
            __syncwarp();
        }
        __syncthreads();

        // ---- phase 1: L0 K=64 N=128 (+As[src]+Ad[dst]+ce), A1 -> A0 ----
        mma_half(smem, E_A1, E_W0, row0, 64, 136, h * 64, 4, acc);
        {
            const float4* as4 = (const float4*)g_As + (size_t)s_src[row] * 32;
            const float4* ad4 = (const float4*)g_Ad + (size_t)s_dst[row] * 32;
#pragma unroll
            for (int n = 0; n < 4; n++) {
                wmma::store_matrix_sync(stg, acc[n], 20, wmma::mem_row_major);
                __syncwarp();
                int col = h * 64 + n * 16 + c0;
                float4 a0 = __ldg(as4 + (col >> 2)), a1 = __ldg(as4 + (col >> 2) + 1);
                float4 d0 = __ldg(ad4 + (col >> 2)), d1 = __ldg(ad4 + (col >> 2) + 1);
                float ga[8] = {a0.x + d0.x, a0.y + d0.y, a0.z + d0.z, a0.w + d0.w,
                               a1.x + d1.x, a1.y + d1.y, a1.z + d1.z, a1.w + d1.w};
                float v[8];
#pragma unroll
                for (int j = 0; j < 8; j++)
                    v[j] = sp(stg[r * 20 + c0 + j] + ga[j] + s_ce[col + j]);
                store_A8(smem, E_A0, row, col, v);
                __syncwarp();
            }
        }
        __syncthreads();

        // ---- phase 2: L1 K=128 N=128, A0 -> A1 ----
        mma_half(smem, E_A0, E_W1, row0, 128, 136, h * 64, 4, acc);
#pragma unroll
        for (int n = 0; n < 4; n++) {
            wmma::store_matrix_sync(stg, acc[n], 20, wmma::mem_row_major);
            __syncwarp();
            int col = h * 64 + n * 16 + c0;
            float v[8];
#pragma unroll
            for (int j = 0; j < 8; j++) v[j] = sp(stg[r * 20 + c0 + j] + s_b1[col + j]);
            store_A8(smem, E_A1, row, col, v);
            __syncwarp();
        }
        __syncthreads();

        // ---- phase 3: L2 K=128 N=64, A1 -> global + fstage(A0) ----
        mma_half(smem, E_A1, E_W2, row0, 128, 72, h * 32, 2, acc);
        {
            int dnode = s_dst[row];
#pragma unroll
            for (int n = 0; n < 2; n++) {
                wmma::store_matrix_sync(stg, acc[n], 20, wmma::mem_row_major);
                __syncwarp();
                int col = h * 32 + n * 16 + c0;
                float v[8];
#pragma unroll
                for (int j = 0; j < 8; j++)
                    v[j] = sp(stg[r * 20 + c0 + j] + s_b2[col + j]);
                size_t gidx = (base + row) * 64 + col;
                float4 e0 = __ldg((const float4*)(ef + gidx));
                float4 e1 = __ldg((const float4*)(ef + gidx) + 1);
                float4 o0 = {v[0] + e0.x, v[1] + e0.y, v[2] + e0.z, v[3] + e0.w};
                float4 o1 = {v[4] + e1.x, v[5] + e1.y, v[6] + e1.z, v[7] + e1.w};
                *(float4*)(e_out + gidx) = o0;
                *((float4*)(e_out + gidx) + 1) = o1;
                float* vrow = &g_ve[(size_t)dnode * 64 + col];
#pragma unroll
                for (int j = 0; j < 8; j++) {
                    atomicAdd(vrow + j, v[j]);
                    fstage[row * 68 + col + j] = v[j];
                }
                if (n == 0 && h == 0 && (lane & 1) == 0)
                    atomicAdd(&g_cnt[dnode], 1.0f);
                __syncwarp();
            }
        }
        __syncthreads();

        // ue partial: 512 threads, 16 rows each
        {
            int col = tid & 63, q = tid >> 6;
            float s = 0.0f;
#pragma unroll
            for (int rr = q * 16; rr < q * 16 + 16; rr++) s += fstage[rr * 68 + col];
            spart[tid] = s;
        }
        __syncthreads();
        if (tid < 64) {
            float s = 0.0f;
#pragma unroll
            for (int q = 0; q < 8; q++) s += spart[q * 64 + tid];
            ue_acc += s;
        }
    }
    if (tid < 64) atomicAdd(&g_ue[tid], ue_acc);
}

// ---------------------------------------------------------------------------
// persistent node kernel: 128 nodes / iteration, 512 threads
// ping-pong: L0 A0->A1, L1 A1->A0, L2 A0 -> global + fstage(A1)
// ---------------------------------------------------------------------------
__global__ __launch_bounds__(512) void node_kernel(
    const float* __restrict__ nf, const float* __restrict__ b1,
    const float* __restrict__ b2, float* __restrict__ v_out, int nNodes,
    int nTiles) {
    extern __shared__ char smem[];
    int tid = threadIdx.x, wid = tid >> 5, lane = tid & 31;

    float* s_cn  = (float*)(smem + N_MISC);
    float* s_b1  = (float*)(smem + N_MISC + 512);
    float* s_b2  = (float*)(smem + N_MISC + 1024);
    float* spart = (float*)(smem + N_MISC + 1280);
    float* stg   = (float*)(smem + N_STG) + wid * 320;
    float* fstage = (float*)(smem + N_A1);

    load_W_seg(smem, 36864, 128, 128, 136, N_W0, tid, 512);
    load_W_seg(smem, 53248, 128, 128, 136, N_W1, tid, 512);
    load_W_seg(smem, 69632, 128, 64,  72, N_W2, tid, 512);
    if (tid < 128) {
        s_cn[tid] = g_cn[tid];
        s_b1[tid] = __ldg(b1 + tid);
    } else if (tid < 192) {
        s_b2[tid - 128] = (tid - 128 < 64) ? __ldg(b2 + tid - 128) : 0.0f;
    }

    int slab = wid & 7, h = wid >> 3, row0 = slab * 16;
    int r = lane >> 1, c0 = (lane & 1) * 8, row = row0 + r;
    float uv_acc = 0.0f;
    FragC acc[4];

    for (int t = blockIdx.x; t < nTiles; t += gridDim.x) {
        size_t base = (size_t)t * 128;
        __syncthreads();

        // stage X = [v_pre | ve_mean] (K=128) -> A0
        {
            int rr = tid & 127, hh = tid >> 7;  // hh 0..3
            size_t gn = base + rr;
            if (gn >= (size_t)nNodes) gn = nNodes - 1;
            const float4* g4;
            float scale = 1.0f;
            if (hh < 2) {
                g4 = (const float4*)(g_v_pre + gn * 64) + hh * 8;
            } else {
                g4 = (const float4*)(g_ve + gn * 64) + (hh - 2) * 8;
                scale = 1.0f / fmaxf(g_cnt[gn], 1.0f);
            }
#pragma unroll
            for (int q = 0; q < 8; q++) {
                float4 v = __ldg(g4 + q);
                v.x *= scale; v.y *= scale; v.z *= scale; v.w *= scale;
                int c = hh * 32 + q * 4;
                *(u32*)(smem + N_A0 + (rr * SA + c) * 2) = pack2h(v.x, v.y);
                *(u32*)(smem + N_A0 + (rr * SA + c + 2) * 2) = pack2h(v.z, v.w);
            }
        }
        __syncthreads();

        bool valid = (base + row) < (size_t)nNodes;

        // ---- L0: K=128 N=128, A0 -> A1 ----
        mma_half(smem, N_A0, N_W0, row0, 128, 136, h * 64, 4, acc);
#pragma unroll
        for (int n = 0; n < 4; n++) {
            wmma::store_matrix_sync(stg, acc[n], 20, wmma::mem_row_major);
            __syncwarp();
            int col = h * 64 + n * 16 + c0;
            float v[8];
#pragma unroll
            for (int j = 0; j < 8; j++) v[j] = sp(stg[r * 20 + c0 + j] + s_cn[col + j]);
            store_A8(smem, N_A1, row, col, v);
            __syncwarp();
        }
        __syncthreads();

        // ---- L1: K=128 N=128, A1 -> A0 ----
        mma_half(smem, N_A1, N_W1, row0, 128, 136, h * 64, 4, acc);
#pragma unroll
        for (int n = 0; n < 4; n++) {
            wmma::store_matrix_sync(stg, acc[n], 20, wmma::mem_row_major);
            __syncwarp();
            int col = h * 64 + n * 16 + c0;
            float v[8];
#pragma unroll
            for (int j = 0; j < 8; j++) v[j] = sp(stg[r * 20 + c0 + j] + s_b1[col + j]);
            store_A8(smem, N_A0, row, col, v);
            __syncwarp();
        }
        __syncthreads();

        // ---- L2: K=128 N=64, A0 -> global + fstage(A1) ----
        mma_half(smem, N_A0, N_W2, row0, 128, 72, h * 32, 2, acc);
#pragma unroll
        for (int n = 0; n < 2; n++) {
            wmma::store_matrix_sync(stg, acc[n], 20, wmma::mem_row_major);
            __syncwarp();
            int col = h * 32 + n * 16 + c0;
            float v[8];
#pragma unroll
            for (int j = 0; j < 8; j++) v[j] = sp(stg[r * 20 + c0 + j] + s_b2[col + j]);
            if (valid) {
                size_t gidx = (base + row) * 64 + col;
                float4 e0 = __ldg((const float4*)(nf + gidx));
                float4 e1 = __ldg((const float4*)(nf + gidx) + 1);
                float4 o0 = {v[0] + e0.x, v[1] + e0.y, v[2] + e0.z, v[3] + e0.w};
                float4 o1 = {v[4] + e1.x, v[5] + e1.y, v[6] + e1.z, v[7] + e1.w};
                *(float4*)(v_out + gidx) = o0;
                *((float4*)(v_out + gidx) + 1) = o1;
            }
#pragma unroll
            for (int j = 0; j < 8; j++)
                fstage[row * 68 + col + j] = valid ? v[j] : 0.0f;
            __syncwarp();
        }
        __syncthreads();

        {
            int col = tid & 63, q = tid >> 6;
            float s = 0.0f;
#pragma unroll
            for (int rr = q * 16; rr < q * 16 + 16; rr++) s += fstage[rr * 68 + col];
            spart[tid] = s;
        }
        __syncthreads();
        if (tid < 64) {
            float s = 0.0f;
#pragma unroll
            for (int q = 0; q < 8; q++) s += spart[q * 64 + tid];
            uv_acc += s;
        }
    }
    if (tid < 64) atomicAdd(&g_uv[tid], uv_acc);
}

// ---------------------------------------------------------------------------
__global__ void attr_kernel(const float* __restrict__ ga,
                            const float* __restrict__ w0,
                            const float* __restrict__ b0,
                            const float* __restrict__ w1,
                            const float* __restrict__ b1,
                            const float* __restrict__ w2,
                            const float* __restrict__ b2,
                            float* __restrict__ out, float invE, float invN) {
    __shared__ float x[192], h0[128], h1[128];
    int t = threadIdx.x;
    if (t < 64) {
        x[t]       = g_u_pre[t];
        x[64 + t]  = g_ue[t] * invE;
        x[128 + t] = g_uv[t] * invN;
    }
    __syncthreads();
    float acc = b0[t];
    for (int k = 0; k < 192; k++) acc = fmaf(x[k], w0[k * 128 + t], acc);
    h0[t] = sp(acc);
    __syncthreads();
    acc = b1[t];
    for (int k = 0; k < 128; k++) acc = fmaf(h0[k], w1[k * 128 + t], acc);
    h1[t] = sp(acc);
    __syncthreads();
    if (t < 64) {
        float a = b2[t];
        for (int k = 0; k < 128; k++) a = fmaf(h1[k], w2[k * 64 + t], a);
        out[t] = sp(a) + ga[t];
    }
}

// ---------------------------------------------------------------------------
extern "C" void kernel_launch(void* const* d_in, const int* in_sizes, int n_in,
                              void* d_out, int out_size) {
    const float* edge_feat  = (const float*)d_in[0];
    const float* node_feat  = (const float*)d_in[1];
    const float* graph_attr = (const float*)d_in[2];
    const int*   src        = (const int*)d_in[3];
    const int*   dst        = (const int*)d_in[4];
    const float* pre_edge_w = (const float*)d_in[5];
    const float* pre_edge_b = (const float*)d_in[6];
    const float* pre_node_w = (const float*)d_in[7];
    const float* pre_node_b = (const float*)d_in[8];
    const float* pre_attr_w = (const float*)d_in[9];
    const float* pre_attr_b = (const float*)d_in[10];
    const float* edge_w0 = (const float*)d_in[11];
    const float* edge_b0 = (const float*)d_in[12];
    const float* edge_w1 = (const float*)d_in[13];
    const float* edge_b1 = (const float*)d_in[14];
    const float* edge_w2 = (const float*)d_in[15];
    const float* edge_b2 = (const float*)d_in[16];
    const float* node_w0 = (const float*)d_in[17];
    const float* node_b0 = (const float*)d_in[18];
    const float* node_w1 = (const float*)d_in[19];
    const float* node_b1 = (const float*)d_in[20];
    const float* node_w2 = (const float*)d_in[21];
    const float* node_b2 = (const float*)d_in[22];
    const float* attr_w0 = (const float*)d_in[23];
    const float* attr_b0 = (const float*)d_in[24];
    const float* attr_w1 = (const float*)d_in[25];
    const float* attr_b1 = (const float*)d_in[26];
    const float* attr_w2 = (const float*)d_in[27];
    const float* attr_b2 = (const float*)d_in[28];

    float* out = (float*)d_out;
    int E = in_sizes[3];
    int N = in_sizes[1] / 64;
    int eTiles = E / 128;
    int nTiles = (N + 127) / 128;

    cudaFuncSetAttribute(edge_kernel, cudaFuncAttributeMaxDynamicSharedMemorySize,
                         E_TOTAL);
    cudaFuncSetAttribute(node_kernel, cudaFuncAttributeMaxDynamicSharedMemorySize,
                         N_TOTAL);

    zero_kernel<<<256, 256>>>(N);
    pre_attr_kernel<<<1, 64>>>(graph_attr, pre_attr_w, pre_attr_b);
    const_kernel<<<1, 128>>>(edge_w0, edge_b0, node_w0, node_b0);
    prep_w_kernel<<<64, 256>>>(pre_edge_w, edge_w0, edge_w1, edge_w2, node_w0,
                               node_w1, node_w2);
    pre_nodeA_kernel<<<N / 32, 128>>>(node_feat, pre_node_w, pre_node_b, edge_w0);
    edge_kernel<<<NUM_CTAS, 512, E_TOTAL>>>(edge_feat, src, dst, pre_edge_b,
                                            edge_b1, edge_b2, out, eTiles);
    node_kernel<<<NUM_CTAS, 512, N_TOTAL>>>(node_feat, node_b1, node_b2,
                                            out + (size_t)E * 64, N, nTiles);
    attr_kernel<<<1, 128>>>(graph_attr, attr_w0, attr_b0, attr_w1, attr_b1,
                            attr_w2, attr_b2,
                            out + (size_t)E * 64 + (size_t)N * 64,
                            1.0f / (float)E, 1.0f / (float)N);
}